// round 1
// baseline (speedup 1.0000x reference)
#include <cuda_runtime.h>
#include <cuda_bf16.h>

#define CANVAS 1024
#define NSH 64
#define TEXN 512

// Per-shape precomputed record: 16 x 32-bit words = 64B.
struct __align__(16) ShapeRec {
    float ax, bx, cx;      // tex_x = ax*px + bx*py + cx
    float ay, by, cy;      // tex_y = ay*px + by*py + cy
    float r, g, b;         // color
    float bx0, bx1, by0, by1;  // canvas-space bbox (conservative)
    int   tex;             // texture index 0..3
    float pad0, pad1;
};

__device__ ShapeRec g_recs[NSH];
__device__ float4   g_tex[4 * TEXN * TEXN];   // interleaved RGBA, 16 MB scratch

// ---------------------------------------------------------------------------
// Kernel 1: per-shape affine linearization + bbox (64 threads)
// ---------------------------------------------------------------------------
__global__ void prep_shapes_kernel(const int* __restrict__ st,
                                   const float* __restrict__ params) {
    int i = threadIdx.x;
    if (i >= NSH) return;
    const float* p = params + i * 9;
    float tx = p[0] * (float)CANVAS;
    float ty = p[1] * (float)CANVAS;
    float W  = (float)CANVAS * (0.05f + 0.95f * p[2]);
    float H  = (float)CANVAS * (0.05f + 0.95f * p[3]);
    float as = p[4], ac = p[5];
    float nrm = sqrtf(as * as + ac * ac) + 1e-8f;
    float c = ac / nrm, s = as / nrm;

    ShapeRec rec;
    float fx = (float)TEXN / W;
    float fy = (float)TEXN / H;
    // tex_x = ((c*dx + s*dy)/W + 0.5)*T - 0.5
    rec.ax = c * fx;
    rec.bx = s * fx;
    rec.cx = (-c * tx - s * ty) * fx + 0.5f * TEXN - 0.5f;
    // tex_y = ((-s*dx + c*dy)/H + 0.5)*T - 0.5
    rec.ay = -s * fy;
    rec.by =  c * fy;
    rec.cy = (s * tx - c * ty) * fy + 0.5f * TEXN - 0.5f;
    rec.r = p[6]; rec.g = p[7]; rec.b = p[8];

    // Conservative bbox: valid tex range (-1, T) maps to |u| <= W/2 * (1 + 2/T).
    float uh = 0.5f * W * (1.0f + 2.0f / TEXN) + 2.0f;
    float vh = 0.5f * H * (1.0f + 2.0f / TEXN) + 2.0f;
    float ex = fabsf(c) * uh + fabsf(s) * vh;
    float ey = fabsf(s) * uh + fabsf(c) * vh;
    rec.bx0 = tx - ex; rec.bx1 = tx + ex;
    rec.by0 = ty - ey; rec.by1 = ty + ey;
    rec.tex = st[i];
    rec.pad0 = 0.f; rec.pad1 = 0.f;
    g_recs[i] = rec;
}

// ---------------------------------------------------------------------------
// Kernel 2: planar [tex][chan][y][x] -> interleaved float4 RGBA
// ---------------------------------------------------------------------------
__global__ void interleave_kernel(const float* __restrict__ tex) {
    int idx = blockIdx.x * blockDim.x + threadIdx.x;
    const int NPIX = TEXN * TEXN;
    if (idx >= 4 * NPIX) return;
    int t = idx >> 18;          // / (512*512)
    int pix = idx & (NPIX - 1);
    const float* base = tex + (size_t)t * 4 * NPIX;
    g_tex[idx] = make_float4(base[pix],
                             base[NPIX + pix],
                             base[2 * NPIX + pix],
                             base[3 * NPIX + pix]);
}

// ---------------------------------------------------------------------------
// Kernel 3: render. One thread per pixel, 32x8 tiles, bbox tile-cull.
// ---------------------------------------------------------------------------
__global__ __launch_bounds__(256) void render_kernel(float* __restrict__ out) {
    __shared__ ShapeRec sh[NSH];
    {
        float4* dst = reinterpret_cast<float4*>(sh);
        const float4* src = reinterpret_cast<const float4*>(g_recs);
        int tid = threadIdx.y * 32 + threadIdx.x;
        const int n = NSH * sizeof(ShapeRec) / 16;   // 256
        if (tid < n) dst[tid] = src[tid];
    }
    __syncthreads();

    int x = blockIdx.x * 32 + threadIdx.x;
    int y = blockIdx.y * 8 + threadIdx.y;
    float px = (float)x + 0.5f;
    float py = (float)y + 0.5f;

    // tile bounds (pixel centers)
    float tX0 = (float)(blockIdx.x * 32) + 0.5f;
    float tX1 = tX0 + 31.0f;
    float tY0 = (float)(blockIdx.y * 8) + 0.5f;
    float tY1 = tY0 + 7.0f;

    float R = 1.0f, G = 1.0f, B = 1.0f;

    #pragma unroll 4
    for (int si = 0; si < NSH; si++) {
        const ShapeRec rec = sh[si];
        // block-uniform bbox cull
        if (tX1 < rec.bx0 || tX0 > rec.bx1 || tY1 < rec.by0 || tY0 > rec.by1)
            continue;

        float u = fmaf(rec.ax, px, fmaf(rec.bx, py, rec.cx));
        float v = fmaf(rec.ay, px, fmaf(rec.by, py, rec.cy));
        // outside (-1, T): all taps have zero weight or zero value -> no-op
        if (!(u > -1.0f && u < (float)TEXN && v > -1.0f && v < (float)TEXN))
            continue;

        float xf = floorf(u), yf = floorf(v);
        float wx = u - xf,    wy = v - yf;
        int xi = (int)xf, yi = (int)yf;

        const float4* tb = g_tex + (size_t)rec.tex * (TEXN * TEXN);
        float4 v00, v01, v10, v11;
        if (xi >= 0 && yi >= 0 && xi < TEXN - 1 && yi < TEXN - 1) {
            const float4* row = tb + yi * TEXN + xi;
            v00 = __ldg(row);
            v01 = __ldg(row + 1);
            v10 = __ldg(row + TEXN);
            v11 = __ldg(row + TEXN + 1);
        } else {
            // edge path with per-tap validity (matches reference zero-fill)
            #define TAP(yy, xx)                                                  \
                [&]() -> float4 {                                                \
                    bool ok = ((unsigned)(xx) < TEXN) && ((unsigned)(yy) < TEXN);\
                    int xc = min(max((xx), 0), TEXN - 1);                        \
                    int yc = min(max((yy), 0), TEXN - 1);                        \
                    float4 t = __ldg(tb + yc * TEXN + xc);                       \
                    if (!ok) t = make_float4(0.f, 0.f, 0.f, 0.f);                \
                    return t;                                                    \
                }()
            v00 = TAP(yi, xi);
            v01 = TAP(yi, xi + 1);
            v10 = TAP(yi + 1, xi);
            v11 = TAP(yi + 1, xi + 1);
            #undef TAP
        }

        float w00 = (1.0f - wx) * (1.0f - wy);
        float w01 = wx * (1.0f - wy);
        float w10 = (1.0f - wx) * wy;
        float w11 = wx * wy;

        float sr = fmaf(v00.x, w00, fmaf(v01.x, w01, fmaf(v10.x, w10, v11.x * w11)));
        float sg = fmaf(v00.y, w00, fmaf(v01.y, w01, fmaf(v10.y, w10, v11.y * w11)));
        float sb = fmaf(v00.z, w00, fmaf(v01.z, w01, fmaf(v10.z, w10, v11.z * w11)));
        float sa = fmaf(v00.w, w00, fmaf(v01.w, w01, fmaf(v10.w, w10, v11.w * w11)));

        float om = 1.0f - sa;
        R = fmaf(R, om, sr * rec.r * sa);
        G = fmaf(G, om, sg * rec.g * sa);
        B = fmaf(B, om, sb * rec.b * sa);
    }

    int o = y * CANVAS + x;
    out[o] = R;
    out[CANVAS * CANVAS + o] = G;
    out[2 * CANVAS * CANVAS + o] = B;
}

// ---------------------------------------------------------------------------
extern "C" void kernel_launch(void* const* d_in, const int* in_sizes, int n_in,
                              void* d_out, int out_size) {
    const int*   shape_type = (const int*)d_in[0];
    const float* params     = (const float*)d_in[1];
    const float* textures   = (const float*)d_in[2];
    float* out = (float*)d_out;

    prep_shapes_kernel<<<1, NSH>>>(shape_type, params);

    const int ntex = 4 * TEXN * TEXN;
    interleave_kernel<<<(ntex + 255) / 256, 256>>>(textures);

    dim3 blk(32, 8);
    dim3 grd(CANVAS / 32, CANVAS / 8);
    render_kernel<<<grd, blk>>>(out);
}

// round 3
// speedup vs baseline: 1.2553x; 1.2553x over previous
#include <cuda_runtime.h>
#include <cuda_fp16.h>

#define CANVAS 1024
#define NSH 64
#define TEXN 512
#define QDIM 513                 // tap-origin range: -1..511
#define QPIX (QDIM * QDIM)      // 263169 entries per texture

// One quad entry = the 2x2 bilinear tap block for tap-origin (yi, xi):
//   a: v00.rg, v00.ba, v01.rg, v01.ba   (halves packed as half2)
//   b: v10.rg, v10.ba, v11.rg, v11.ba
// Out-of-bounds taps are stored as zero (matches reference zero-fill).
struct __align__(32) Quad { uint4 a, b; };

__device__ Quad g_quad[4 * QPIX];   // 4 tex * 513^2 * 32B = ~33.7 MB scratch

// Per-shape record, built in shared memory by each render block.
struct ShapeRec {
    float tx, ty;               // shape center in canvas px
    float m00, m01, m10, m11;   // tex = M * (p - t) + 255.5
    float r, g, b;
    float bx0, bx1, by0, by1;   // conservative canvas bbox
    int   texoff;               // t * QPIX
    float pad0, pad1;
};

// ---------------------------------------------------------------------------
// Kernel 1: build fp16 quad-gather table from planar f32 textures.
// grid: (QDIM rows, 4 tex), block 256; each block sweeps one row (513 wide)
// so adjacent threads touch adjacent texels -> coalesced planar reads.
// ---------------------------------------------------------------------------
__global__ __launch_bounds__(256) void build_quad_kernel(const float* __restrict__ tex) {
    int t  = blockIdx.y;
    int yi = (int)blockIdx.x - 1;          // -1..511
    const int NPIX = TEXN * TEXN;
    const float* base = tex + (size_t)t * 4 * NPIX;
    Quad* qrow = g_quad + t * QPIX + blockIdx.x * QDIM;

    for (int xq = threadIdx.x; xq < QDIM; xq += 256) {
        int xi = xq - 1;                   // -1..511

        float vals[4][4];  // [tap][chan]
        #pragma unroll
        for (int ty2 = 0; ty2 < 2; ty2++) {
            #pragma unroll
            for (int tx2 = 0; tx2 < 2; tx2++) {
                int y = yi + ty2, x = xi + tx2;
                bool ok = ((unsigned)x < (unsigned)TEXN) && ((unsigned)y < (unsigned)TEXN);
                int off = y * TEXN + x;
                #pragma unroll
                for (int ch = 0; ch < 4; ch++)
                    vals[ty2 * 2 + tx2][ch] = ok ? __ldg(base + ch * NPIX + off) : 0.0f;
            }
        }

        __half2 h[8];
        #pragma unroll
        for (int tap = 0; tap < 4; tap++) {
            h[tap * 2 + 0] = __floats2half2_rn(vals[tap][0], vals[tap][1]);  // r,g
            h[tap * 2 + 1] = __floats2half2_rn(vals[tap][2], vals[tap][3]);  // b,a
        }

        Quad q;
        q.a = *reinterpret_cast<uint4*>(&h[0]);
        q.b = *reinterpret_cast<uint4*>(&h[4]);
        qrow[xq] = q;
    }
}

// ---------------------------------------------------------------------------
// Kernel 2: render. One thread per pixel. Shape prep fused into smem fill.
// ---------------------------------------------------------------------------
__global__ __launch_bounds__(256) void render_kernel(const int* __restrict__ st,
                                                     const float* __restrict__ params,
                                                     float* __restrict__ out) {
    __shared__ ShapeRec sh[NSH];

    int tid = threadIdx.y * 32 + threadIdx.x;
    if (tid < NSH) {
        const float* p = params + tid * 9;
        float tx = p[0] * (float)CANVAS;
        float ty = p[1] * (float)CANVAS;
        float W  = (float)CANVAS * (0.05f + 0.95f * p[2]);
        float H  = (float)CANVAS * (0.05f + 0.95f * p[3]);
        float as = p[4], ac = p[5];
        float nrm = sqrtf(as * as + ac * ac) + 1e-8f;
        float c = ac / nrm, s = as / nrm;
        float fx = (float)TEXN / W;
        float fy = (float)TEXN / H;

        ShapeRec rec;
        rec.tx = tx; rec.ty = ty;
        rec.m00 =  c * fx;  rec.m01 = s * fx;
        rec.m10 = -s * fy;  rec.m11 = c * fy;
        rec.r = p[6]; rec.g = p[7]; rec.b = p[8];

        float uh = 0.5f * W * (1.0f + 2.0f / TEXN) + 2.0f;
        float vh = 0.5f * H * (1.0f + 2.0f / TEXN) + 2.0f;
        float ex = fabsf(c) * uh + fabsf(s) * vh;
        float ey = fabsf(s) * uh + fabsf(c) * vh;
        rec.bx0 = tx - ex; rec.bx1 = tx + ex;
        rec.by0 = ty - ey; rec.by1 = ty + ey;
        rec.texoff = st[tid] * QPIX;
        rec.pad0 = rec.pad1 = 0.f;
        sh[tid] = rec;
    }
    __syncthreads();

    int x = blockIdx.x * 32 + threadIdx.x;
    int y = blockIdx.y * 8 + threadIdx.y;
    float px = (float)x + 0.5f;
    float py = (float)y + 0.5f;

    float tX0 = (float)(blockIdx.x * 32) + 0.5f;
    float tX1 = tX0 + 31.0f;
    float tY0 = (float)(blockIdx.y * 8) + 0.5f;
    float tY1 = tY0 + 7.0f;

    float R = 1.0f, G = 1.0f, B = 1.0f;

    #pragma unroll 4
    for (int si = 0; si < NSH; si++) {
        const ShapeRec rec = sh[si];
        // block-uniform bbox cull
        if (tX1 < rec.bx0 || tX0 > rec.bx1 || tY1 < rec.by0 || tY0 > rec.by1)
            continue;

        // local-frame coords: small operands, no catastrophic cancellation
        float dx = px - rec.tx;
        float dy = py - rec.ty;
        float u = fmaf(rec.m00, dx, fmaf(rec.m01, dy, 255.5f));
        float v = fmaf(rec.m10, dx, fmaf(rec.m11, dy, 255.5f));
        // outside (-1, T): every tap is zero or zero-weighted -> no-op
        if (!(u > -1.0f && u < (float)TEXN && v > -1.0f && v < (float)TEXN))
            continue;

        float xf = floorf(u), yf = floorf(v);
        float wx = u - xf,    wy = v - yf;
        int xi = (int)xf, yi = (int)yf;   // -1..511

        const uint4* q = reinterpret_cast<const uint4*>(
            g_quad + rec.texoff + (yi + 1) * QDIM + (xi + 1));
        uint4 qa = __ldg(q);
        uint4 qb = __ldg(q + 1);

        float w00 = (1.0f - wx) * (1.0f - wy);
        float w01 = wx * (1.0f - wy);
        float w10 = (1.0f - wx) * wy;
        float w11 = wx * wy;

        float2 rg00 = __half22float2(*reinterpret_cast<const __half2*>(&qa.x));
        float2 ba00 = __half22float2(*reinterpret_cast<const __half2*>(&qa.y));
        float2 rg01 = __half22float2(*reinterpret_cast<const __half2*>(&qa.z));
        float2 ba01 = __half22float2(*reinterpret_cast<const __half2*>(&qa.w));
        float2 rg10 = __half22float2(*reinterpret_cast<const __half2*>(&qb.x));
        float2 ba10 = __half22float2(*reinterpret_cast<const __half2*>(&qb.y));
        float2 rg11 = __half22float2(*reinterpret_cast<const __half2*>(&qb.z));
        float2 ba11 = __half22float2(*reinterpret_cast<const __half2*>(&qb.w));

        float sr = fmaf(rg00.x, w00, fmaf(rg01.x, w01, fmaf(rg10.x, w10, rg11.x * w11)));
        float sg = fmaf(rg00.y, w00, fmaf(rg01.y, w01, fmaf(rg10.y, w10, rg11.y * w11)));
        float sb = fmaf(ba00.x, w00, fmaf(ba01.x, w01, fmaf(ba10.x, w10, ba11.x * w11)));
        float sa = fmaf(ba00.y, w00, fmaf(ba01.y, w01, fmaf(ba10.y, w10, ba11.y * w11)));

        float om = 1.0f - sa;
        R = fmaf(R, om, sr * rec.r * sa);
        G = fmaf(G, om, sg * rec.g * sa);
        B = fmaf(B, om, sb * rec.b * sa);
    }

    int o = y * CANVAS + x;
    out[o] = R;
    out[CANVAS * CANVAS + o] = G;
    out[2 * CANVAS * CANVAS + o] = B;
}

// ---------------------------------------------------------------------------
extern "C" void kernel_launch(void* const* d_in, const int* in_sizes, int n_in,
                              void* d_out, int out_size) {
    const int*   shape_type = (const int*)d_in[0];
    const float* params     = (const float*)d_in[1];
    const float* textures   = (const float*)d_in[2];
    float* out = (float*)d_out;

    dim3 bgrid(QDIM, 4);
    build_quad_kernel<<<bgrid, 256>>>(textures);

    dim3 blk(32, 8);
    dim3 grd(CANVAS / 32, CANVAS / 8);
    render_kernel<<<grd, blk>>>(shape_type, params, out);
}